// round 8
// baseline (speedup 1.0000x reference)
#include <cuda_runtime.h>
#include <cuda_fp16.h>

// Problem constants
#define BATCH    128
#define SEQT     256
#define HID      128
#define WIN      16
#define NSTEP    3840          // (256-16)*16 chained LSTM steps
#define NTHREADS 512           // 16 warps; warp w owns gate rows [32w, 32w+32)

// Named barriers (1: activated gates ready -> combine; 2: h ready -> all)
#define BAR_ARRIVE(id) asm volatile("bar.arrive %0, %1;" :: "r"(id), "r"(NTHREADS) : "memory")
#define BAR_SYNC(id)   asm volatile("bar.sync %0, %1;"   :: "r"(id), "r"(NTHREADS) : "memory")

// HW tanh (MUFU.TANH) and sigmoid via tanh
__device__ __forceinline__ float tanh_fast(float x) {
    float y; asm("tanh.approx.f32 %0, %1;" : "=f"(y) : "f"(x)); return y;
}
__device__ __forceinline__ float sigm_fast(float x) {
    return __fmaf_rn(0.5f, tanh_fast(0.5f * x), 0.5f);
}
__device__ __forceinline__ unsigned pack_h2(float lo, float hi) {
    __half2 h = __floats2half2_rn(lo, hi);
    return *reinterpret_cast<unsigned*>(&h);
}
// m16n8k16 row.col f16*f16 -> f32 accumulate (warp-level HMMA)
__device__ __forceinline__ void mma16816(float* c, const unsigned* a, unsigned b0, unsigned b1) {
    asm volatile(
        "mma.sync.aligned.m16n8k16.row.col.f32.f16.f16.f32 "
        "{%0,%1,%2,%3},{%4,%5,%6,%7},{%8,%9},{%0,%1,%2,%3};\n"
        : "+f"(c[0]), "+f"(c[1]), "+f"(c[2]), "+f"(c[3])
        : "r"(a[0]), "r"(a[1]), "r"(a[2]), "r"(a[3]), "r"(b0), "r"(b1));
}

__global__ void __launch_bounds__(NTHREADS, 1)
lstm_mma6_kernel(const float* __restrict__ x,
                 const float* __restrict__ W_ih,
                 const float* __restrict__ W_hh,
                 const float* __restrict__ b_ih,
                 const float* __restrict__ b_hh,
                 const float* __restrict__ fc_W,
                 const float* __restrict__ fc_b,
                 float* __restrict__ out)
{
    __shared__ float sx[SEQT];
    // Activated gates, packed as float2{row R+gid, row R+gid+8} per 16-row tile:
    // slot for gate row r: pair index (r/16)*8 + (r%8), component (r%16)/8.
    __shared__ __align__(16) float2 sg2[256];
    __shared__ __align__(16) __half sh_hi[HID];       // h (fp16 high)
    __shared__ __align__(16) __half sh_lo[HID];       // h residual (fp16)
    __shared__ float sred[4];

    const int tid = threadIdx.x;
    const int b   = blockIdx.x;
    const int w   = tid >> 5;          // warp 0..15
    const int l   = tid & 31;
    const int gid = l >> 2;            // 0..7  (frag row group / B column)
    const int tg  = l & 3;             // 0..3
    const bool combiner = (w >= 12);   // warps 12-15 run the cell combine
    const int  cu = tid - 384;         // combiner's hidden unit (0..127)
    // Gate type of this warp's rows: warps 0-3 -> i, 4-7 -> f, 8-11 -> g, 12-15 -> o
    const bool gate_is_tanh = (w >= 8 && w < 12);

    // ---------------- Prologue: A fragments (W_hh fp16, resident in RF) ----
    unsigned Afrag[2][8][4];
#pragma unroll
    for (int t = 0; t < 2; ++t) {
        const int R = 32 * w + 16 * t;
        const float* r0 = W_hh + (R + gid)     * HID;
        const float* r8 = W_hh + (R + gid + 8) * HID;
#pragma unroll
        for (int kk = 0; kk < 8; ++kk) {
            const int k0 = 16 * kk + 2 * tg;
            Afrag[t][kk][0] = pack_h2(r0[k0],     r0[k0 + 1]);
            Afrag[t][kk][1] = pack_h2(r8[k0],     r8[k0 + 1]);
            Afrag[t][kk][2] = pack_h2(r0[k0 + 8], r0[k0 + 9]);
            Afrag[t][kk][3] = pack_h2(r8[k0 + 8], r8[k0 + 9]);
        }
    }

    // Per-lane bias / W_ih for rows (gid, gid+8) of each tile (used at tg==0)
    float biasr[2][2], wihr[2][2];
#pragma unroll
    for (int t = 0; t < 2; ++t) {
        const int R = 32 * w + 16 * t;
        biasr[t][0] = b_ih[R + gid]     + b_hh[R + gid];
        biasr[t][1] = b_ih[R + gid + 8] + b_hh[R + gid + 8];
        wihr[t][0]  = W_ih[R + gid];
        wihr[t][1]  = W_ih[R + gid + 8];
    }

    const float fcw = combiner ? fc_W[cu] : 0.f;
    const float fcb = fc_b[0];
    float c_state = 0.f;

    if (tid < HID) {
        sh_hi[tid] = __float2half_rn(0.f);
        sh_lo[tid] = __float2half_rn(0.f);
    }
    if (tid < SEQT) sx[tid] = x[b * SEQT + tid];
    if (tid < WIN)  out[b * SEQT + tid] = x[b * SEQT + tid];
    __syncthreads();

    // Combiner gate slot addresses (activated values):
    //   row r -> sg2[(r/16)*8 + (r%8)] component (r%16)/8
    const float* sgf = (const float*)sg2;
    const int sl_i = ((cu      >> 4) << 4) + ((cu & 15) & 7) * 2 + (((cu      & 15) >> 3));
    const int sl_f = ((((cu + 128) >> 4) << 4)) + ((cu & 7) * 2) + ((cu & 15) >> 3);
    const int sl_g = ((((cu + 256) >> 4) << 4)) + ((cu & 7) * 2) + ((cu & 15) >> 3);
    const int sl_o = ((((cu + 384) >> 4) << 4)) + ((cu & 7) * 2) + ((cu & 15) >> 3);

    // B-column content: col 1 (gid==1) = h_lo; all other columns read h_hi
    const __half* bp = (gid == 1) ? sh_lo : sh_hi;

    // ---------------- 3840 chained steps -----------------------------------
    for (int s = 0; s < NSTEP; ++s) {
        const float xt = sx[(s >> 4) + (s & (WIN - 1))];

        // Two half-depth chains per tile: cA (kk 0..3) + cB (kk 4..7).
        float cA[2][4], cB[2][4];
#pragma unroll
        for (int t = 0; t < 2; ++t) {
            if (tg == 0) {
                cA[t][0] = __fmaf_rn(xt, wihr[t][0], biasr[t][0]);
                cA[t][2] = __fmaf_rn(xt, wihr[t][1], biasr[t][1]);
            } else {
                cA[t][0] = 0.f; cA[t][2] = 0.f;
            }
            cA[t][1] = 0.f; cA[t][3] = 0.f;
            cB[t][0] = 0.f; cB[t][1] = 0.f; cB[t][2] = 0.f; cB[t][3] = 0.f;
        }

#pragma unroll
        for (int kk = 0; kk < 4; ++kk) {
            unsigned b0 = *(const unsigned*)(bp + 16 * kk + 2 * tg);
            unsigned b1 = *(const unsigned*)(bp + 16 * kk + 8 + 2 * tg);
            mma16816(cA[0], Afrag[0][kk], b0, b1);
            mma16816(cA[1], Afrag[1][kk], b0, b1);
        }
#pragma unroll
        for (int kk = 4; kk < 8; ++kk) {
            unsigned b0 = *(const unsigned*)(bp + 16 * kk + 2 * tg);
            unsigned b1 = *(const unsigned*)(bp + 16 * kk + 8 + 2 * tg);
            mma16816(cB[0], Afrag[0][kk], b0, b1);
            mma16816(cB[1], Afrag[1][kk], b0, b1);
        }

        // tg==0: raw gate = (col0 hi) + (col1 lo); activate HERE (producer side),
        // then store both rows of each tile with one STS.64.
        if (tg == 0) {
#pragma unroll
            for (int t = 0; t < 2; ++t) {
                float v0 = (cA[t][0] + cB[t][0]) + (cA[t][1] + cB[t][1]);
                float v1 = (cA[t][2] + cB[t][2]) + (cA[t][3] + cB[t][3]);
                float a0, a1;
                if (gate_is_tanh) { a0 = tanh_fast(v0); a1 = tanh_fast(v1); }
                else              { a0 = sigm_fast(v0); a1 = sigm_fast(v1); }
                sg2[(2 * w + t) * 8 + gid] = make_float2(a0, a1);
            }
        }

        if (!combiner) {
            BAR_ARRIVE(1);
            BAR_SYNC(2);
        } else {
            BAR_SYNC(1);

            // All values pre-activated: short dependent chain.
            const float ai = sgf[sl_i];
            const float af = sgf[sl_f];
            const float tg_ = sgf[sl_g];
            const float ao = sgf[sl_o];
            c_state = __fmaf_rn(af, c_state, ai * tg_);
            const float h = ao * tanh_fast(c_state);

            const __half hh = __float2half_rn(h);
            sh_hi[cu] = hh;
            sh_lo[cu] = __float2half_rn(h - __half2float(hh));

            if ((s & (WIN - 1)) == (WIN - 1)) {            // fc tap at t=15
                float p = fcw * h;
                p += __shfl_down_sync(0xffffffffu, p, 16);
                p += __shfl_down_sync(0xffffffffu, p, 8);
                p += __shfl_down_sync(0xffffffffu, p, 4);
                p += __shfl_down_sync(0xffffffffu, p, 2);
                p += __shfl_down_sync(0xffffffffu, p, 1);
                if (l == 0) sred[w - 12] = p;
            }
            BAR_SYNC(2);

            if (((s & (WIN - 1)) == (WIN - 1)) && tid == 384) {
                float v = sred[0] + sred[1] + sred[2] + sred[3] + fcb;
                out[b * SEQT + WIN + (s >> 4)] = (v >= 0.f) ? v : 0.3f * v;
            }
        }
    }
}

extern "C" void kernel_launch(void* const* d_in, const int* in_sizes, int n_in,
                              void* d_out, int out_size)
{
    const float* x    = (const float*)d_in[0];
    const float* W_ih = (const float*)d_in[1];
    const float* W_hh = (const float*)d_in[2];
    const float* b_ih = (const float*)d_in[3];
    const float* b_hh = (const float*)d_in[4];
    const float* fc_W = (const float*)d_in[5];
    const float* fc_b = (const float*)d_in[6];

    lstm_mma6_kernel<<<BATCH, NTHREADS>>>(
        x, W_ih, W_hh, b_ih, b_hh, fc_W, fc_b, (float*)d_out);
}

// round 9
// speedup vs baseline: 1.0475x; 1.0475x over previous
#include <cuda_runtime.h>
#include <cuda_fp16.h>

// Problem constants
#define BATCH    128
#define SEQT     256
#define HID      128
#define WIN      16
#define NSTEP    3840          // (256-16)*16 chained LSTM steps
#define NTHREADS 512           // 16 warps; warp w owns gate rows [32w, 32w+32)

// Named barriers (1: sg ready -> combine; 2: h ready -> everyone)
#define BAR_ARRIVE(id) asm volatile("bar.arrive %0, %1;" :: "r"(id), "r"(NTHREADS) : "memory")
#define BAR_SYNC(id)   asm volatile("bar.sync %0, %1;"   :: "r"(id), "r"(NTHREADS) : "memory")

// HW tanh (MUFU.TANH) and sigmoid via tanh
__device__ __forceinline__ float tanh_fast(float x) {
    float y; asm("tanh.approx.f32 %0, %1;" : "=f"(y) : "f"(x)); return y;
}
__device__ __forceinline__ float sigm_fast(float x) {
    return __fmaf_rn(0.5f, tanh_fast(0.5f * x), 0.5f);
}
__device__ __forceinline__ unsigned pack_h2(float lo, float hi) {
    __half2 h = __floats2half2_rn(lo, hi);
    return *reinterpret_cast<unsigned*>(&h);
}
// m16n8k16 row.col f16*f16 -> f32 accumulate (warp-level HMMA)
__device__ __forceinline__ void mma16816(float* c, const unsigned* a, unsigned b0, unsigned b1) {
    asm volatile(
        "mma.sync.aligned.m16n8k16.row.col.f32.f16.f16.f32 "
        "{%0,%1,%2,%3},{%4,%5,%6,%7},{%8,%9},{%0,%1,%2,%3};\n"
        : "+f"(c[0]), "+f"(c[1]), "+f"(c[2]), "+f"(c[3])
        : "r"(a[0]), "r"(a[1]), "r"(a[2]), "r"(a[3]), "r"(b0), "r"(b1));
}

__global__ void __launch_bounds__(NTHREADS, 1)
lstm_mma7_kernel(const float* __restrict__ x,
                 const float* __restrict__ W_ih,
                 const float* __restrict__ W_hh,
                 const float* __restrict__ b_ih,
                 const float* __restrict__ b_hh,
                 const float* __restrict__ fc_W,
                 const float* __restrict__ fc_b,
                 float* __restrict__ out)
{
    __shared__ float sx[SEQT];
    // Gate-major raw gates: sgu[4*unit + gate] (gate: 0=i,1=f,2=g,3=o)
    __shared__ __align__(16) float sgu[4 * HID];
    __shared__ __align__(16) __half sh_hi[HID];       // h (fp16 high, trunc)
    __shared__ __align__(16) __half sh_lo[HID];       // h residual (fp16)
    __shared__ float sred[4];

    const int tid = threadIdx.x;
    const int b   = blockIdx.x;
    const int w   = tid >> 5;          // warp 0..15
    const int l   = tid & 31;
    const int gid = l >> 2;            // 0..7  (frag row group / B column)
    const int tg  = l & 3;             // 0..3
    const int gate = w >> 2;           // 0=i,1=f,2=g,3=o (warp's gate block)
    const bool combiner = (w >= 12);   // warps 12-15 run the cell combine
    const int  cu = tid - 384;         // combiner's hidden unit (0..127)

    // ---------------- Prologue: A fragments (W_hh fp16, resident in RF) ----
    unsigned Afrag[2][8][4];
#pragma unroll
    for (int t = 0; t < 2; ++t) {
        const int R = 32 * w + 16 * t;
        const float* r0 = W_hh + (R + gid)     * HID;
        const float* r8 = W_hh + (R + gid + 8) * HID;
#pragma unroll
        for (int kk = 0; kk < 8; ++kk) {
            const int k0 = 16 * kk + 2 * tg;
            Afrag[t][kk][0] = pack_h2(r0[k0],     r0[k0 + 1]);
            Afrag[t][kk][1] = pack_h2(r8[k0],     r8[k0 + 1]);
            Afrag[t][kk][2] = pack_h2(r0[k0 + 8], r0[k0 + 9]);
            Afrag[t][kk][3] = pack_h2(r8[k0 + 8], r8[k0 + 9]);
        }
    }

    // Per-lane bias / W_ih for rows (gid, gid+8) of each tile (used at tg==0)
    float biasr[2][2], wihr[2][2];
#pragma unroll
    for (int t = 0; t < 2; ++t) {
        const int R = 32 * w + 16 * t;
        biasr[t][0] = b_ih[R + gid]     + b_hh[R + gid];
        biasr[t][1] = b_ih[R + gid + 8] + b_hh[R + gid + 8];
        wihr[t][0]  = W_ih[R + gid];
        wihr[t][1]  = W_ih[R + gid + 8];
    }

    const float fcw = combiner ? fc_W[cu] : 0.f;
    const float fcb = fc_b[0];
    float c_state = 0.f;

    if (tid < HID) {
        sh_hi[tid] = __float2half_rn(0.f);
        sh_lo[tid] = __float2half_rn(0.f);
    }
    if (tid < SEQT) sx[tid] = x[b * SEQT + tid];
    if (tid < WIN)  out[b * SEQT + tid] = x[b * SEQT + tid];
    __syncthreads();

    // Producer STS slots: unit u = 32*(w&3) + 16*t + gid (and u+8)
    int sts0[2], sts1[2];
#pragma unroll
    for (int t = 0; t < 2; ++t) {
        const int u0 = 32 * (w & 3) + 16 * t + gid;
        sts0[t] = 4 * u0 + gate;
        sts1[t] = 4 * (u0 + 8) + gate;
    }

    // B-column content: col 1 (gid==1) = h_lo; all other columns read h_hi
    const __half* bp = (gid == 1) ? sh_lo : sh_hi;

    // ---------------- 3840 chained steps -----------------------------------
    for (int s = 0; s < NSTEP; ++s) {
        const float xt = sx[(s >> 4) + (s & (WIN - 1))];

        // Two half-depth chains per tile: cA (kk 0..3) + cB (kk 4..7).
        float cA[2][4], cB[2][4];
#pragma unroll
        for (int t = 0; t < 2; ++t) {
            if (tg == 0) {
                cA[t][0] = __fmaf_rn(xt, wihr[t][0], biasr[t][0]);
                cA[t][2] = __fmaf_rn(xt, wihr[t][1], biasr[t][1]);
            } else {
                cA[t][0] = 0.f; cA[t][2] = 0.f;
            }
            cA[t][1] = 0.f; cA[t][3] = 0.f;
            cB[t][0] = 0.f; cB[t][1] = 0.f; cB[t][2] = 0.f; cB[t][3] = 0.f;
        }

#pragma unroll
        for (int kk = 0; kk < 4; ++kk) {
            unsigned b0 = *(const unsigned*)(bp + 16 * kk + 2 * tg);
            unsigned b1 = *(const unsigned*)(bp + 16 * kk + 8 + 2 * tg);
            mma16816(cA[0], Afrag[0][kk], b0, b1);
            mma16816(cA[1], Afrag[1][kk], b0, b1);
        }
#pragma unroll
        for (int kk = 4; kk < 8; ++kk) {
            unsigned b0 = *(const unsigned*)(bp + 16 * kk + 2 * tg);
            unsigned b1 = *(const unsigned*)(bp + 16 * kk + 8 + 2 * tg);
            mma16816(cB[0], Afrag[0][kk], b0, b1);
            mma16816(cB[1], Afrag[1][kk], b0, b1);
        }

        // tg==0 lanes: raw gate = (col0 hi) + (col1 lo); gate-major layout.
        if (tg == 0) {
#pragma unroll
            for (int t = 0; t < 2; ++t) {
                sgu[sts0[t]] = (cA[t][0] + cB[t][0]) + (cA[t][1] + cB[t][1]);
                sgu[sts1[t]] = (cA[t][2] + cB[t][2]) + (cA[t][3] + cB[t][3]);
            }
        }

        if (!combiner) {
            // Producers: post sg, then block only once (until h is ready).
            BAR_ARRIVE(1);
            BAR_SYNC(2);
        } else {
            // Combiners (warps 12-15, highest arbiter priority): wait for sg.
            BAR_SYNC(1);

            // One LDS.128 fetches all four gates of unit cu.
            const float4 gv = *(const float4*)(sgu + 4 * cu);
            c_state = sigm_fast(gv.y) * c_state + sigm_fast(gv.x) * tanh_fast(gv.z);
            const float h = sigm_fast(gv.w) * tanh_fast(c_state);

            // Truncation split: hi has 10-bit mantissa (exact in fp16),
            // lo = h - hi exact in fp32; the two F2FP converts are parallel.
            const float hi_f = __uint_as_float(__float_as_uint(h) & 0xFFFFE000u);
            const float lo_f = h - hi_f;
            sh_hi[cu] = __float2half_rn(hi_f);
            sh_lo[cu] = __float2half_rn(lo_f);

            if ((s & (WIN - 1)) == (WIN - 1)) {            // fc tap at t=15
                float p = fcw * h;
                p += __shfl_down_sync(0xffffffffu, p, 16);
                p += __shfl_down_sync(0xffffffffu, p, 8);
                p += __shfl_down_sync(0xffffffffu, p, 4);
                p += __shfl_down_sync(0xffffffffu, p, 2);
                p += __shfl_down_sync(0xffffffffu, p, 1);
                if (l == 0) sred[w - 12] = p;
            }
            BAR_SYNC(2);

            if (((s & (WIN - 1)) == (WIN - 1)) && tid == 384) {
                float v = sred[0] + sred[1] + sred[2] + sred[3] + fcb;
                out[b * SEQT + WIN + (s >> 4)] = (v >= 0.f) ? v : 0.3f * v;
            }
        }
    }
}

extern "C" void kernel_launch(void* const* d_in, const int* in_sizes, int n_in,
                              void* d_out, int out_size)
{
    const float* x    = (const float*)d_in[0];
    const float* W_ih = (const float*)d_in[1];
    const float* W_hh = (const float*)d_in[2];
    const float* b_ih = (const float*)d_in[3];
    const float* b_hh = (const float*)d_in[4];
    const float* fc_W = (const float*)d_in[5];
    const float* fc_b = (const float*)d_in[6];

    lstm_mma7_kernel<<<BATCH, NTHREADS>>>(
        x, W_ih, W_hh, b_ih, b_hh, fc_W, fc_b, (float*)d_out);
}

// round 10
// speedup vs baseline: 1.1715x; 1.1184x over previous
#include <cuda_runtime.h>
#include <cuda_fp16.h>

// Problem constants
#define BATCH    128
#define SEQT     256
#define HID      128
#define WIN      16
#define NSTEP    3840          // (256-16)*16 chained LSTM steps
#define NTHREADS 512           // 16 warps; warp w owns gate rows [32w, 32w+32)

// Named barriers (1: sg ready -> combine; 2: h ready -> everyone)
#define BAR_ARRIVE(id) asm volatile("bar.arrive %0, %1;" :: "r"(id), "r"(NTHREADS) : "memory")
#define BAR_SYNC(id)   asm volatile("bar.sync %0, %1;"   :: "r"(id), "r"(NTHREADS) : "memory")

// HW tanh (MUFU.TANH) and sigmoid via tanh
__device__ __forceinline__ float tanh_fast(float x) {
    float y; asm("tanh.approx.f32 %0, %1;" : "=f"(y) : "f"(x)); return y;
}
__device__ __forceinline__ float sigm_fast(float x) {
    return __fmaf_rn(0.5f, tanh_fast(0.5f * x), 0.5f);
}
__device__ __forceinline__ unsigned pack_h2(float lo, float hi) {
    __half2 h = __floats2half2_rn(lo, hi);
    return *reinterpret_cast<unsigned*>(&h);
}
// m16n8k16 row.col f16*f16 -> f32 accumulate (warp-level HMMA)
__device__ __forceinline__ void mma16816(float* c, const unsigned* a, unsigned b0, unsigned b1) {
    asm volatile(
        "mma.sync.aligned.m16n8k16.row.col.f32.f16.f16.f32 "
        "{%0,%1,%2,%3},{%4,%5,%6,%7},{%8,%9},{%0,%1,%2,%3};\n"
        : "+f"(c[0]), "+f"(c[1]), "+f"(c[2]), "+f"(c[3])
        : "r"(a[0]), "r"(a[1]), "r"(a[2]), "r"(a[3]), "r"(b0), "r"(b1));
}

__global__ void __launch_bounds__(NTHREADS, 1)
lstm_mma8_kernel(const float* __restrict__ x,
                 const float* __restrict__ W_ih,
                 const float* __restrict__ W_hh,
                 const float* __restrict__ b_ih,
                 const float* __restrict__ b_hh,
                 const float* __restrict__ fc_W,
                 const float* __restrict__ fc_b,
                 float* __restrict__ out)
{
    __shared__ float sx[SEQT];
    __shared__ float sg[4 * HID];                 // raw gates, row-major (R7 layout)
    // h in B-FRAGMENT ORDER: u32 slot (kk*8 + tg*2 + b3) = half2 for
    // k = 16kk + 8*b3 + 2tg (+1). b0/b1 of one k-step are adjacent -> LDS.64.
    __shared__ __align__(16) unsigned shB_hi[64]; // 128 halves (h high part)
    __shared__ __align__(16) unsigned shB_lo[64]; // 128 halves (h residual)
    __shared__ float sred[4];

    const int tid = threadIdx.x;
    const int b   = blockIdx.x;
    const int w   = tid >> 5;          // warp 0..15
    const int l   = tid & 31;
    const int gid = l >> 2;            // 0..7  (frag row group / B column)
    const int tg  = l & 3;             // 0..3
    const bool combiner = (w >= 12);   // warps 12-15 run the cell combine
    const int  cu = tid - 384;         // combiner's hidden unit (0..127)

    // ---------------- Prologue: A fragments (W_hh fp16, resident in RF) ----
    unsigned Afrag[2][8][4];
#pragma unroll
    for (int t = 0; t < 2; ++t) {
        const int R = 32 * w + 16 * t;
        const float* r0 = W_hh + (R + gid)     * HID;
        const float* r8 = W_hh + (R + gid + 8) * HID;
#pragma unroll
        for (int kk = 0; kk < 8; ++kk) {
            const int k0 = 16 * kk + 2 * tg;
            Afrag[t][kk][0] = pack_h2(r0[k0],     r0[k0 + 1]);
            Afrag[t][kk][1] = pack_h2(r8[k0],     r8[k0 + 1]);
            Afrag[t][kk][2] = pack_h2(r0[k0 + 8], r0[k0 + 9]);
            Afrag[t][kk][3] = pack_h2(r8[k0 + 8], r8[k0 + 9]);
        }
    }

    // Per-lane bias / W_ih for rows (gid, gid+8) of each tile (used at tg==0)
    float biasr[2][2], wihr[2][2];
#pragma unroll
    for (int t = 0; t < 2; ++t) {
        const int R = 32 * w + 16 * t;
        biasr[t][0] = b_ih[R + gid]     + b_hh[R + gid];
        biasr[t][1] = b_ih[R + gid + 8] + b_hh[R + gid + 8];
        wihr[t][0]  = W_ih[R + gid];
        wihr[t][1]  = W_ih[R + gid + 8];
    }

    const float fcw = combiner ? fc_W[cu] : 0.f;
    const float fcb = fc_b[0];
    float c_state = 0.f;

    if (tid < 64) { shB_hi[tid] = 0u; shB_lo[tid] = 0u; }    // h0 = 0
    if (tid < SEQT) sx[tid] = x[b * SEQT + tid];
    if (tid < WIN)  out[b * SEQT + tid] = x[b * SEQT + tid];
    __syncthreads();

    // Combiner's h-store byte offset in the fragment-ordered buffer:
    //   kk=cu>>4, b3=(cu>>3)&1, tg=(cu>>1)&3, e=cu&1
    const int frag_off = combiner
        ? (((cu >> 4) << 5) + (((cu >> 1) & 3) << 3) + (((cu >> 3) & 1) << 2) + ((cu & 1) << 1))
        : 0;
    __half* sthi = (__half*)((char*)shB_hi + frag_off);
    __half* stlo = (__half*)((char*)shB_lo + frag_off);

    // B-operand base: column gid==1 reads h_lo; all others read h_hi
    // (cols 2..7 are valid dummy loads, their D columns are never consumed).
    const char* bpc = (const char*)((gid == 1) ? shB_lo : shB_hi);

    // ---------------- 3840 chained steps -----------------------------------
    for (int s = 0; s < NSTEP; ++s) {
        const float xt = sx[(s >> 4) + (s & (WIN - 1))];

        // Two half-depth chains per tile: cA (kk 0..3) + cB (kk 4..7).
        float cA[2][4], cB[2][4];
#pragma unroll
        for (int t = 0; t < 2; ++t) {
            if (tg == 0) {
                cA[t][0] = __fmaf_rn(xt, wihr[t][0], biasr[t][0]);
                cA[t][2] = __fmaf_rn(xt, wihr[t][1], biasr[t][1]);
            } else {
                cA[t][0] = 0.f; cA[t][2] = 0.f;
            }
            cA[t][1] = 0.f; cA[t][3] = 0.f;
            cB[t][0] = 0.f; cB[t][1] = 0.f; cB[t][2] = 0.f; cB[t][3] = 0.f;
        }

        // One LDS.64 per k-step fetches {b0, b1}.
#pragma unroll
        for (int kk = 0; kk < 4; ++kk) {
            const uint2 bb = *(const uint2*)(bpc + kk * 32 + tg * 8);
            mma16816(cA[0], Afrag[0][kk], bb.x, bb.y);
            mma16816(cA[1], Afrag[1][kk], bb.x, bb.y);
        }
#pragma unroll
        for (int kk = 4; kk < 8; ++kk) {
            const uint2 bb = *(const uint2*)(bpc + kk * 32 + tg * 8);
            mma16816(cB[0], Afrag[0][kk], bb.x, bb.y);
            mma16816(cB[1], Afrag[1][kk], bb.x, bb.y);
        }

        // tg==0 lanes: raw gate = (col0 hi) + (col1 lo). R7 row-major sg.
        if (tg == 0) {
#pragma unroll
            for (int t = 0; t < 2; ++t) {
                const int R = 32 * w + 16 * t;
                sg[R + gid]     = (cA[t][0] + cB[t][0]) + (cA[t][1] + cB[t][1]);
                sg[R + gid + 8] = (cA[t][2] + cB[t][2]) + (cA[t][3] + cB[t][3]);
            }
        }

        if (!combiner) {
            // Producers: post sg, then block only once (until h is ready).
            BAR_ARRIVE(1);
            BAR_SYNC(2);
        } else {
            // Combiners (warps 12-15, highest arbiter priority): wait for sg.
            BAR_SYNC(1);

            const float gi = sg[cu];
            const float gf = sg[cu + HID];
            const float gg = sg[cu + 2 * HID];
            const float go = sg[cu + 3 * HID];
            c_state = sigm_fast(gf) * c_state + sigm_fast(gi) * tanh_fast(gg);
            const float h = sigm_fast(go) * tanh_fast(c_state);

            const __half hh = __float2half_rn(h);
            *sthi = hh;
            *stlo = __float2half_rn(h - __half2float(hh));

            if ((s & (WIN - 1)) == (WIN - 1)) {            // fc tap at t=15
                float p = fcw * h;
                p += __shfl_down_sync(0xffffffffu, p, 16);
                p += __shfl_down_sync(0xffffffffu, p, 8);
                p += __shfl_down_sync(0xffffffffu, p, 4);
                p += __shfl_down_sync(0xffffffffu, p, 2);
                p += __shfl_down_sync(0xffffffffu, p, 1);
                if (l == 0) sred[w - 12] = p;
            }
            BAR_SYNC(2);

            if (((s & (WIN - 1)) == (WIN - 1)) && tid == 384) {
                float v = sred[0] + sred[1] + sred[2] + sred[3] + fcb;
                out[b * SEQT + WIN + (s >> 4)] = (v >= 0.f) ? v : 0.3f * v;
            }
        }
    }
}

extern "C" void kernel_launch(void* const* d_in, const int* in_sizes, int n_in,
                              void* d_out, int out_size)
{
    const float* x    = (const float*)d_in[0];
    const float* W_ih = (const float*)d_in[1];
    const float* W_hh = (const float*)d_in[2];
    const float* b_ih = (const float*)d_in[3];
    const float* b_hh = (const float*)d_in[4];
    const float* fc_W = (const float*)d_in[5];
    const float* fc_b = (const float*)d_in[6];

    lstm_mma8_kernel<<<BATCH, NTHREADS>>>(
        x, W_ih, W_hh, b_ih, b_hh, fc_W, fc_b, (float*)d_out);
}